// round 3
// baseline (speedup 1.0000x reference)
#include <cuda_runtime.h>
#include <math.h>

#define BATCH   4096
#define VOCAB   100000
#define NTRI    3276      // canonical triples p<=q<=j, 26 fields
#define NPAIR2  351       // canonical pairs p<=q
#define NT4     1121      // sum over pairs of (7 - q/4) float4 runs

// ---------------- scratch (device globals) ----------------
__device__ float g_V[128 * 26];       // V[i,j] = sum_o2 clinW[128+o2]*W1[o2,i,j]
__device__ float g_V0c[NPAIR2];       // symmetric-folded V0 pairs
__device__ float g_Tc[NTRI];          // canonical triple coefficients
__device__ float g_Tc4[NT4 * 4];      // float4-padded runs per pair
__device__ float g_vb[26];            // vb[j] = sum_i V[i,j]*b0[i]
__device__ float g_cadd;              // 8*(clinW[:128].b0 + clinW[128:].b1)
__device__ float g_emb[BATCH * 208];  // [b][j][k]
__device__ float g_lin[BATCH];
__device__ float g_s1[BATCH];
__device__ float g_s2[BATCH];
__device__ float g_h1[BATCH * 256];
__device__ float g_h2[BATCH * 128];

// ---------------- prep 0: V, V0c, scalar ----------------
__global__ void k_prep0(const float* __restrict__ W0, const float* __restrict__ W1,
                        const float* __restrict__ clinW,
                        const float* __restrict__ b0, const float* __restrict__ b1) {
    int t0 = blockIdx.x * blockDim.x + threadIdx.x;
    int stride = gridDim.x * blockDim.x;
    for (int u = t0; u < 128 * 26; u += stride) {
        float s = 0.f;
        #pragma unroll 8
        for (int o = 0; o < 128; o++) s += clinW[128 + o] * W1[o * 3328 + u];
        g_V[u] = s;
    }
    for (int t2 = t0; t2 < NPAIR2; t2 += stride) {
        int rem = t2, p = 0;
        while (rem >= 26 - p) { rem -= 26 - p; p++; }
        int q = p + rem;
        float s = 0.f;
        for (int o = 0; o < 128; o++) {
            float w = W0[o * 676 + p * 26 + q];
            if (p < q) w += W0[o * 676 + q * 26 + p];
            s += clinW[o] * w;
        }
        g_V0c[t2] = s;
    }
    if (t0 == 0) {
        float s = 0.f;
        for (int o = 0; o < 128; o++) s += clinW[o] * b0[o] + clinW[128 + o] * b1[o];
        g_cadd = 8.f * s;
    }
}

// ---------------- prep 1: canonical triple coeffs + vb ----------------
__global__ void k_prep1(const float* __restrict__ W0, const float* __restrict__ b0) {
    int t = blockIdx.x * blockDim.x + threadIdx.x;
    if (t < NTRI) {
        int rem = t, p = 0;
        while (true) { int cnt = (26 - p) * (27 - p) / 2; if (rem < cnt) break; rem -= cnt; p++; }
        int q = p;
        while (true) { int cnt = 26 - q; if (rem < cnt) break; rem -= cnt; q++; }
        int j = q + rem;
        float s = 0.f;
        for (int i = 0; i < 128; i++) {
            const float* w = W0 + i * 676;
            float vp = g_V[i * 26 + p], vq = g_V[i * 26 + q], vj = g_V[i * 26 + j];
            if (p == q && q == j) {
                s += vp * w[p * 26 + p];
            } else if (p == q) {
                s += vj * w[p * 26 + p] + vp * (w[p * 26 + j] + w[j * 26 + p]);
            } else if (q == j) {
                s += vp * w[q * 26 + q] + vq * (w[p * 26 + q] + w[q * 26 + p]);
            } else {
                s += vj * (w[p * 26 + q] + w[q * 26 + p])
                   + vq * (w[p * 26 + j] + w[j * 26 + p])
                   + vp * (w[q * 26 + j] + w[j * 26 + q]);
            }
        }
        g_Tc[t] = s;
    } else if (t < NTRI + 26) {
        int j = t - NTRI;
        float s = 0.f;
        for (int i = 0; i < 128; i++) s += g_V[i * 26 + j] * b0[i];
        g_vb[j] = s;
    }
}

// ---------------- prep 2: pack triple coeffs into float4-aligned runs ----------------
__global__ void k_prep2() {
    int t2 = blockIdx.x * blockDim.x + threadIdx.x;
    if (t2 >= NPAIR2) return;
    int s4 = 0, bt = 0, p = -1, q = -1, cnt = 0;
    for (int pp = 0; pp < 26 && p < 0; pp++)
        for (int qq = pp; qq < 26; qq++) {
            if (cnt == t2) { p = pp; q = qq; break; }
            s4 += 7 - (qq >> 2); bt += 26 - qq; cnt++;
        }
    int q0 = q & ~3;
    int nfl = (7 - (q >> 2)) * 4;
    for (int pos = 0; pos < nfl; pos++) {
        int j = q0 + pos;
        float v = (j >= q && j < 26) ? g_Tc[bt + (j - q)] : 0.f;
        g_Tc4[s4 * 4 + pos] = v;
    }
}

// ---------------- gather embeddings + linear term ----------------
__global__ void k_gather(const float* __restrict__ inputs,
                         const float* __restrict__ emb_tables,
                         const float* __restrict__ linW,
                         const float* __restrict__ linb) {
    int warp = (blockIdx.x * blockDim.x + threadIdx.x) >> 5;
    int lane = threadIdx.x & 31;
    if (warp >= BATCH) return;
    int b = warp;
    const float* row = inputs + b * 39;
    if (lane < 26) {
        int idx = (int)row[13 + lane];
        const float4* src = (const float4*)(emb_tables + ((size_t)lane * VOCAB + idx) * 8);
        float4* dst = (float4*)(g_emb + b * 208 + lane * 8);
        dst[0] = src[0];
        dst[1] = src[1];
    }
    float s = 0.f;
    for (int t = lane; t < 39; t += 32) s += row[t] * linW[t];
    #pragma unroll
    for (int o = 16; o; o >>= 1) s += __shfl_down_sync(0xffffffffu, s, o);
    if (lane == 0) g_lin[b] = s + linb[0];
}

// ---------------- CIN as third-moment contraction ----------------
// thread = (sample-in-block, k); 16 samples/block, grid 256.
__global__ __launch_bounds__(128) void k_cin() {
    __shared__ float4 Tc4s[NT4];
    __shared__ float V0s[NPAIR2];
    __shared__ float vbs[26];
    __shared__ __align__(16) float Et[128 * 28];
    int tid = threadIdx.x;
    int b0 = blockIdx.x * 16;

    for (int t = tid; t < NT4; t += 128) Tc4s[t] = ((const float4*)g_Tc4)[t];
    for (int t = tid; t < NPAIR2; t += 128) V0s[t] = g_V0c[t];
    if (tid < 26) vbs[tid] = g_vb[tid];

    int bl = tid >> 3, k = tid & 7;
    float* myE = Et + tid * 28;
    const float* ebase = g_emb + (b0 + bl) * 208 + k;
    #pragma unroll
    for (int j = 0; j < 26; j++) myE[j] = ebase[j * 8];
    myE[26] = 0.f; myE[27] = 0.f;
    __syncthreads();

    float s1p = 0.f, s2p = 0.f;
    int t4 = 0, t2 = 0;
    for (int p = 0; p < 26; p++) {
        float ep = myE[p];
        for (int q = p; q < 26; q++) {
            float w = ep * myE[q];
            s1p = fmaf(V0s[t2++], w, s1p);
            float d0 = 0.f, d1 = 0.f;
            for (int j4 = (q & ~3); j4 < 28; j4 += 4) {
                float4 tc = Tc4s[t4++];
                float4 ev = *(const float4*)&myE[j4];
                d0 = fmaf(tc.x, ev.x, d0);
                d1 = fmaf(tc.y, ev.y, d1);
                d0 = fmaf(tc.z, ev.z, d0);
                d1 = fmaf(tc.w, ev.w, d1);
            }
            s2p = fmaf(w, d0 + d1, s2p);
        }
    }
    #pragma unroll
    for (int j = 0; j < 26; j++) s2p = fmaf(vbs[j], myE[j], s2p);

    #pragma unroll
    for (int off = 4; off; off >>= 1) {
        s1p += __shfl_down_sync(0xffffffffu, s1p, off, 8);
        s2p += __shfl_down_sync(0xffffffffu, s2p, off, 8);
    }
    if (k == 0) {
        g_s1[b0 + bl] = s1p;
        g_s2[b0 + bl] = s2p;
    }
}

// ---------------- MLP layer 1: (4096 x 224pad)@(224 x 256), relu ----------------
// 32x64 tile, 128 threads, double-buffered K=32 tiles.
__global__ __launch_bounds__(128) void k_mlp1(const float* __restrict__ inputs,
                                              const float* __restrict__ W1,
                                              const float* __restrict__ b1) {
    __shared__ float As[2][32 * 33];        // [kk][r] padded
    __shared__ float4 Bs[2][32 * 16];       // [kk][c4]
    int tid = threadIdx.x;
    int b0 = blockIdx.x * 32;
    int n0 = blockIdx.y * 64;
    int r0 = (tid >> 4) << 2;
    int c0 = (tid & 15) << 2;
    int kkA = tid & 31, rA0 = (tid >> 5) * 8;

    float acc[4][4];
    #pragma unroll
    for (int rr = 0; rr < 4; rr++)
        #pragma unroll
        for (int cc = 0; cc < 4; cc++) acc[rr][cc] = 0.f;

    float a_reg[8];
    float4 b_reg[4];

    // prologue: tile 0
    #pragma unroll
    for (int i = 0; i < 8; i++) {
        int b = b0 + rA0 + i, kg = kkA;
        float v = (kg < 13) ? inputs[b * 39 + kg] : g_emb[b * 208 + kg - 13];
        As[0][kkA * 33 + rA0 + i] = v;
    }
    #pragma unroll
    for (int i = 0; i < 4; i++) {
        int t4 = tid + i * 128;
        int kk = t4 >> 4, c4 = t4 & 15;
        Bs[0][kk * 16 + c4] = *(const float4*)&W1[kk * 256 + n0 + c4 * 4];
    }
    __syncthreads();

    for (int kt = 0; kt < 7; kt++) {
        int cur = kt & 1;
        if (kt < 6) {
            int k0 = (kt + 1) * 32;
            #pragma unroll
            for (int i = 0; i < 8; i++) {
                int b = b0 + rA0 + i, kg = k0 + kkA;
                float v = 0.f;
                if (kg < 13) v = inputs[b * 39 + kg];
                else if (kg < 221) v = g_emb[b * 208 + kg - 13];
                a_reg[i] = v;
            }
            #pragma unroll
            for (int i = 0; i < 4; i++) {
                int t4 = tid + i * 128;
                int kk = t4 >> 4, c4 = t4 & 15;
                int kg = k0 + kk;
                b_reg[i] = (kg < 221) ? *(const float4*)&W1[kg * 256 + n0 + c4 * 4]
                                      : make_float4(0.f, 0.f, 0.f, 0.f);
            }
        }
        #pragma unroll 8
        for (int kk = 0; kk < 32; kk++) {
            float a0 = As[cur][kk * 33 + r0 + 0];
            float a1 = As[cur][kk * 33 + r0 + 1];
            float a2 = As[cur][kk * 33 + r0 + 2];
            float a3 = As[cur][kk * 33 + r0 + 3];
            float4 bv = Bs[cur][kk * 16 + (c0 >> 2)];
            float a[4] = {a0, a1, a2, a3};
            float w[4] = {bv.x, bv.y, bv.z, bv.w};
            #pragma unroll
            for (int rr = 0; rr < 4; rr++)
                #pragma unroll
                for (int cc = 0; cc < 4; cc++) acc[rr][cc] = fmaf(a[rr], w[cc], acc[rr][cc]);
        }
        if (kt < 6) {
            int nxt = 1 - cur;
            #pragma unroll
            for (int i = 0; i < 8; i++) As[nxt][kkA * 33 + rA0 + i] = a_reg[i];
            #pragma unroll
            for (int i = 0; i < 4; i++) {
                int t4 = tid + i * 128;
                Bs[nxt][(t4 >> 4) * 16 + (t4 & 15)] = b_reg[i];
            }
        }
        __syncthreads();
    }

    #pragma unroll
    for (int rr = 0; rr < 4; rr++) {
        int b = b0 + r0 + rr;
        float4 v;
        v.x = fmaxf(acc[rr][0] + b1[n0 + c0 + 0], 0.f);
        v.y = fmaxf(acc[rr][1] + b1[n0 + c0 + 1], 0.f);
        v.z = fmaxf(acc[rr][2] + b1[n0 + c0 + 2], 0.f);
        v.w = fmaxf(acc[rr][3] + b1[n0 + c0 + 3], 0.f);
        *(float4*)&g_h1[b * 256 + n0 + c0] = v;
    }
}

// ---------------- MLP layer 2: (4096 x 256)@(256 x 128), relu ----------------
__global__ __launch_bounds__(128) void k_mlp2(const float* __restrict__ W2,
                                              const float* __restrict__ b2) {
    __shared__ float As[2][32 * 33];
    __shared__ float4 Bs[2][32 * 16];
    int tid = threadIdx.x;
    int b0 = blockIdx.x * 32;
    int n0 = blockIdx.y * 64;
    int r0 = (tid >> 4) << 2;
    int c0 = (tid & 15) << 2;
    int kkA = tid & 31, rA0 = (tid >> 5) * 8;

    float acc[4][4];
    #pragma unroll
    for (int rr = 0; rr < 4; rr++)
        #pragma unroll
        for (int cc = 0; cc < 4; cc++) acc[rr][cc] = 0.f;

    float a_reg[8];
    float4 b_reg[4];

    #pragma unroll
    for (int i = 0; i < 8; i++)
        As[0][kkA * 33 + rA0 + i] = g_h1[(b0 + rA0 + i) * 256 + kkA];
    #pragma unroll
    for (int i = 0; i < 4; i++) {
        int t4 = tid + i * 128;
        int kk = t4 >> 4, c4 = t4 & 15;
        Bs[0][kk * 16 + c4] = *(const float4*)&W2[kk * 128 + n0 + c4 * 4];
    }
    __syncthreads();

    for (int kt = 0; kt < 8; kt++) {
        int cur = kt & 1;
        if (kt < 7) {
            int k0 = (kt + 1) * 32;
            #pragma unroll
            for (int i = 0; i < 8; i++)
                a_reg[i] = g_h1[(b0 + rA0 + i) * 256 + k0 + kkA];
            #pragma unroll
            for (int i = 0; i < 4; i++) {
                int t4 = tid + i * 128;
                int kk = t4 >> 4, c4 = t4 & 15;
                b_reg[i] = *(const float4*)&W2[(k0 + kk) * 128 + n0 + c4 * 4];
            }
        }
        #pragma unroll 8
        for (int kk = 0; kk < 32; kk++) {
            float a0 = As[cur][kk * 33 + r0 + 0];
            float a1 = As[cur][kk * 33 + r0 + 1];
            float a2 = As[cur][kk * 33 + r0 + 2];
            float a3 = As[cur][kk * 33 + r0 + 3];
            float4 bv = Bs[cur][kk * 16 + (c0 >> 2)];
            float a[4] = {a0, a1, a2, a3};
            float w[4] = {bv.x, bv.y, bv.z, bv.w};
            #pragma unroll
            for (int rr = 0; rr < 4; rr++)
                #pragma unroll
                for (int cc = 0; cc < 4; cc++) acc[rr][cc] = fmaf(a[rr], w[cc], acc[rr][cc]);
        }
        if (kt < 7) {
            int nxt = 1 - cur;
            #pragma unroll
            for (int i = 0; i < 8; i++) As[nxt][kkA * 33 + rA0 + i] = a_reg[i];
            #pragma unroll
            for (int i = 0; i < 4; i++) {
                int t4 = tid + i * 128;
                Bs[nxt][(t4 >> 4) * 16 + (t4 & 15)] = b_reg[i];
            }
        }
        __syncthreads();
    }

    #pragma unroll
    for (int rr = 0; rr < 4; rr++) {
        int b = b0 + r0 + rr;
        float4 v;
        v.x = fmaxf(acc[rr][0] + b2[n0 + c0 + 0], 0.f);
        v.y = fmaxf(acc[rr][1] + b2[n0 + c0 + 1], 0.f);
        v.z = fmaxf(acc[rr][2] + b2[n0 + c0 + 2], 0.f);
        v.w = fmaxf(acc[rr][3] + b2[n0 + c0 + 3], 0.f);
        *(float4*)&g_h2[b * 128 + n0 + c0] = v;
    }
}

// ---------------- MLP L3 + L4 + combine + sigmoid ----------------
__global__ __launch_bounds__(128) void k_final(const float* __restrict__ W3,
                                               const float* __restrict__ b3,
                                               const float* __restrict__ W4,
                                               const float* __restrict__ b4,
                                               const float* __restrict__ clinb,
                                               float* __restrict__ out) {
    __shared__ float W3s[128 * 64];
    __shared__ float hs[16 * 128];
    __shared__ float W4s[64];
    __shared__ float red[4];
    int tid = threadIdx.x;
    int b0 = blockIdx.x * 16;
    for (int t = tid; t < 128 * 64; t += 128) W3s[t] = W3[t];
    for (int t = tid; t < 16 * 128; t += 128) hs[t] = g_h2[b0 * 128 + t];
    if (tid < 64) W4s[tid] = W4[tid];
    __syncthreads();

    int sh = tid >> 6;
    int o = tid & 63;
    float w4 = W4s[o];
    float b3o = b3[o];
    for (int ss = 0; ss < 8; ss++) {
        int s = ss * 2 + sh;
        float acc = 0.f;
        #pragma unroll 8
        for (int k = 0; k < 128; k++) acc += hs[s * 128 + k] * W3s[k * 64 + o];
        float h3 = fmaxf(acc + b3o, 0.f);
        float p = h3 * w4;
        #pragma unroll
        for (int off = 16; off; off >>= 1) p += __shfl_down_sync(0xffffffffu, p, off);
        if ((tid & 31) == 0) red[tid >> 5] = p;
        __syncthreads();
        if (o == 0) {
            float d = fmaxf(red[sh * 2] + red[sh * 2 + 1] + b4[0], 0.f);
            int b = b0 + s;
            float cin = fmaxf(g_s1[b] + g_s2[b] + g_cadd + clinb[0], 0.f);
            float logit = g_lin[b] + cin + d;
            out[b] = 1.f / (1.f + expf(-logit));
        }
        __syncthreads();
    }
}

// ---------------- launch ----------------
extern "C" void kernel_launch(void* const* d_in, const int* in_sizes, int n_in,
                              void* d_out, int out_size) {
    const float* inputs     = (const float*)d_in[0];
    const float* emb_tables = (const float*)d_in[1];
    const float* linear_W   = (const float*)d_in[2];
    const float* linear_b   = (const float*)d_in[3];
    const float* W_cin0     = (const float*)d_in[4];
    const float* b_cin0     = (const float*)d_in[5];
    const float* W_cin1     = (const float*)d_in[6];
    const float* b_cin1     = (const float*)d_in[7];
    const float* cin_lin_W  = (const float*)d_in[8];
    const float* cin_lin_b  = (const float*)d_in[9];
    const float* d_W1       = (const float*)d_in[10];
    const float* d_b1       = (const float*)d_in[11];
    const float* d_W2       = (const float*)d_in[12];
    const float* d_b2       = (const float*)d_in[13];
    const float* d_W3       = (const float*)d_in[14];
    const float* d_b3       = (const float*)d_in[15];
    const float* d_W4       = (const float*)d_in[16];
    const float* d_b4       = (const float*)d_in[17];
    float* out = (float*)d_out;

    k_prep0<<<32, 256>>>(W_cin0, W_cin1, cin_lin_W, b_cin0, b_cin1);
    k_prep1<<<13, 256>>>(W_cin0, b_cin0);
    k_prep2<<<2, 256>>>();
    k_gather<<<512, 256>>>(inputs, emb_tables, linear_W, linear_b);
    k_cin<<<256, 128>>>();
    k_mlp1<<<dim3(128, 4), 128>>>(inputs, d_W1, d_b1);
    k_mlp2<<<dim3(128, 2), 128>>>(d_W2, d_b2);
    k_final<<<256, 128>>>(d_W3, d_b3, d_W4, d_b4, cin_lin_b, out);
}

// round 4
// speedup vs baseline: 1.2015x; 1.2015x over previous
#include <cuda_runtime.h>
#include <math.h>

#define BATCH   4096
#define VOCAB   100000
#define NTRI    3276
#define NPAIR2  351
#define NT4     1121
#define XDIM    224      // [0:13] dense, [13:16] zero pad, [16:224] emb (26*8)

// ---------------- scratch (device globals) ----------------
__device__ __align__(16) float g_V[128 * 26];
__device__ __align__(16) float g_V0c[NPAIR2];
__device__ __align__(16) float g_T3[NPAIR2 * 26];
__device__ __align__(16) float4 g_Tc4[NT4];
__device__ int   g_runofs[NPAIR2];
__device__ __align__(16) float g_vb[32];
__device__ float g_cadd;
__device__ __align__(16) float g_X[BATCH * XDIM];
__device__ float g_lin[BATCH];
__device__ float g_s1[BATCH];
__device__ float g_s2[BATCH];
__device__ __align__(16) float g_h1[BATCH * 256];
__device__ __align__(16) float g_h2[BATCH * 128];

// ---------------- packed f32x2 helpers ----------------
__device__ __forceinline__ unsigned long long pk2(float lo, float hi) {
    unsigned long long r;
    asm("mov.b64 %0, {%1, %2};" : "=l"(r) : "f"(lo), "f"(hi));
    return r;
}
__device__ __forceinline__ unsigned long long fma2(unsigned long long a,
                                                   unsigned long long b,
                                                   unsigned long long c) {
    unsigned long long d;
    asm("fma.rn.f32x2 %0, %1, %2, %3;" : "=l"(d) : "l"(a), "l"(b), "l"(c));
    return d;
}
__device__ __forceinline__ float2 up2(unsigned long long v) {
    float2 f;
    asm("mov.b64 {%0, %1}, %2;" : "=f"(f.x), "=f"(f.y) : "l"(v));
    return f;
}

// ---------------- prep V: g_V, V0c, runofs, zero Tc4 ----------------
__global__ void k_prepV(const float* __restrict__ W0, const float* __restrict__ W1,
                        const float* __restrict__ clinW) {
    int t0 = blockIdx.x * blockDim.x + threadIdx.x;
    int st = gridDim.x * blockDim.x;
    float* tc4f = (float*)g_Tc4;
    for (int u = t0; u < NT4 * 4; u += st) tc4f[u] = 0.f;
    for (int u = t0; u < 3328; u += st) {
        float s = 0.f;
        #pragma unroll 8
        for (int o = 0; o < 128; o++) s = fmaf(clinW[128 + o], W1[o * 3328 + u], s);
        g_V[u] = s;
    }
    for (int t2 = t0; t2 < NPAIR2; t2 += st) {
        int p = 0, rem = t2;
        while (rem >= 26 - p) { rem -= 26 - p; p++; }
        int q = p + rem;
        const float* wp = W0 + p * 26 + q;
        const float* wq = W0 + q * 26 + p;
        float s = 0.f;
        if (p == q) {
            #pragma unroll 4
            for (int o = 0; o < 128; o++) s = fmaf(clinW[o], wp[o * 676], s);
        } else {
            #pragma unroll 4
            for (int o = 0; o < 128; o++) s = fmaf(clinW[o], wp[o * 676] + wq[o * 676], s);
        }
        g_V0c[t2] = s;
        int s4 = 0;
        for (int pp = 0; pp < p; pp++)
            for (int qq = pp; qq < 26; qq++) s4 += 7 - (qq >> 2);
        for (int qq = p; qq < q; qq++) s4 += 7 - (qq >> 2);
        g_runofs[t2] = s4;
    }
}

// ---------------- prep T3: (351 x 26) = W0sym^T @ V, K=128 ----------------
__global__ __launch_bounds__(64) void k_prepT3(const float* __restrict__ W0) {
    __shared__ float Vs[128 * 26];
    int tid = threadIdx.x;
    for (int t = tid; t < 3328; t += 64) Vs[t] = g_V[t];
    __syncthreads();
    int pq = blockIdx.x * 64 + tid;
    if (pq >= NPAIR2) return;
    int p = 0, rem = pq;
    while (rem >= 26 - p) { rem -= 26 - p; p++; }
    int q = p + rem;
    float acc[26];
    #pragma unroll
    for (int j = 0; j < 26; j++) acc[j] = 0.f;
    const float* wp = W0 + p * 26 + q;
    const float* wq = W0 + q * 26 + p;
    if (p == q) {
        for (int i = 0; i < 128; i++) {
            float w = wp[i * 676];
            #pragma unroll
            for (int j = 0; j < 26; j++) acc[j] = fmaf(w, Vs[i * 26 + j], acc[j]);
        }
    } else {
        for (int i = 0; i < 128; i++) {
            float w = wp[i * 676] + wq[i * 676];
            #pragma unroll
            for (int j = 0; j < 26; j++) acc[j] = fmaf(w, Vs[i * 26 + j], acc[j]);
        }
    }
    #pragma unroll
    for (int j = 0; j < 26; j++) g_T3[pq * 26 + j] = acc[j];
}

// ---------------- prep fold: canonical triple coeffs -> padded runs; vb; cadd ----
__device__ __forceinline__ int pidx(int a, int b) {
    return a * 26 - a * (a - 1) / 2 + (b - a);
}
__global__ void k_prepFold(const float* __restrict__ b0, const float* __restrict__ b1,
                           const float* __restrict__ clinW) {
    int t = blockIdx.x * blockDim.x + threadIdx.x;
    if (t < NTRI) {
        int rem = t, p = 0;
        while (true) { int c = (26 - p) * (27 - p) / 2; if (rem < c) break; rem -= c; p++; }
        int q = p;
        while (true) { int c = 26 - q; if (rem < c) break; rem -= c; q++; }
        int j = q + rem;
        float v;
        if (p == q && q == j)
            v = g_T3[pidx(p, p) * 26 + p];
        else if (p == q)
            v = g_T3[pidx(p, p) * 26 + j] + g_T3[pidx(p, j) * 26 + p];
        else if (q == j)
            v = g_T3[pidx(p, q) * 26 + q] + g_T3[pidx(q, q) * 26 + p];
        else
            v = g_T3[pidx(p, q) * 26 + j] + g_T3[pidx(p, j) * 26 + q]
              + g_T3[pidx(q, j) * 26 + p];
        int q0 = q & ~3;
        ((float*)g_Tc4)[g_runofs[pidx(p, q)] * 4 + (j - q0)] = v;
    } else if (t < NTRI + 26) {
        int j = t - NTRI;
        float s = 0.f;
        #pragma unroll 4
        for (int i = 0; i < 128; i++) s = fmaf(g_V[i * 26 + j], b0[i], s);
        g_vb[j] = s;
    } else if (t >= 3552 && t < 3584) {
        int lane = t - 3552;
        float s = 0.f;
        for (int o = lane; o < 128; o += 32)
            s += clinW[o] * b0[o] + clinW[128 + o] * b1[o];
        #pragma unroll
        for (int off = 16; off; off >>= 1) s += __shfl_down_sync(0xffffffffu, s, off);
        if (lane == 0) g_cadd = 8.f * s;
    }
}

// ---------------- gather: build padded g_X + linear term ----------------
__global__ void k_gather(const float* __restrict__ inputs,
                         const float* __restrict__ emb_tables,
                         const float* __restrict__ linW,
                         const float* __restrict__ linb) {
    int warp = (blockIdx.x * blockDim.x + threadIdx.x) >> 5;
    int lane = threadIdx.x & 31;
    if (warp >= BATCH) return;
    int b = warp;
    const float* row = inputs + b * 39;
    if (lane < 13) g_X[b * XDIM + lane] = row[lane];
    else if (lane < 16) g_X[b * XDIM + lane] = 0.f;
    if (lane < 26) {
        int idx = (int)row[13 + lane];
        const float4* src = (const float4*)(emb_tables + ((size_t)lane * VOCAB + idx) * 8);
        float4* dst = (float4*)(g_X + b * XDIM + 16 + lane * 8);
        dst[0] = src[0];
        dst[1] = src[1];
    }
    float s = 0.f;
    for (int t = lane; t < 39; t += 32) s += row[t] * linW[t];
    #pragma unroll
    for (int o = 16; o; o >>= 1) s += __shfl_down_sync(0xffffffffu, s, o);
    if (lane == 0) g_lin[b] = s + linb[0];
}

// ---------------- CIN: third-moment contraction, e in registers ----------------
__global__ __launch_bounds__(128) void k_cin() {
    __shared__ float4 Tc4s[NT4];
    __shared__ float V0s[NPAIR2];
    __shared__ float vbs[32];
    int tid = threadIdx.x;
    int b0 = blockIdx.x * 16;
    for (int t = tid; t < NT4; t += 128) Tc4s[t] = g_Tc4[t];
    for (int t = tid; t < NPAIR2; t += 128) V0s[t] = g_V0c[t];
    if (tid < 26) vbs[tid] = g_vb[tid];

    int bl = tid >> 3, k = tid & 7;
    const float* eb = g_X + (b0 + bl) * XDIM + 16 + k;
    float e[28];
    #pragma unroll
    for (int j = 0; j < 26; j++) e[j] = eb[j * 8];
    e[26] = 0.f; e[27] = 0.f;
    __syncthreads();

    float s1p = 0.f, s2p = 0.f;
    int t4 = 0, t2 = 0;
    #pragma unroll
    for (int p = 0; p < 26; p++) {
        #pragma unroll
        for (int q = p; q < 26; q++) {
            float w = e[p] * e[q];
            s1p = fmaf(V0s[t2], w, s1p); t2++;
            float d = 0.f;
            #pragma unroll
            for (int j4 = (q & ~3); j4 < 28; j4 += 4) {
                float4 tc = Tc4s[t4]; t4++;
                d = fmaf(tc.x, e[j4 + 0], d);
                d = fmaf(tc.y, e[j4 + 1], d);
                d = fmaf(tc.z, e[j4 + 2], d);
                d = fmaf(tc.w, e[j4 + 3], d);
            }
            s2p = fmaf(w, d, s2p);
        }
    }
    #pragma unroll
    for (int j = 0; j < 26; j++) s2p = fmaf(vbs[j], e[j], s2p);

    #pragma unroll
    for (int off = 4; off; off >>= 1) {
        s1p += __shfl_down_sync(0xffffffffu, s1p, off, 8);
        s2p += __shfl_down_sync(0xffffffffu, s2p, off, 8);
    }
    if (k == 0) {
        g_s1[b0 + bl] = s1p;
        g_s2[b0 + bl] = s2p;
    }
}

// ---------------- MLP1: (4096 x 224)@(224 x 256), relu, f32x2 ----------------
__global__ __launch_bounds__(128) void k_mlp1(const float* __restrict__ W1,
                                              const float* __restrict__ b1) {
    __shared__ float As[32 * 16];   // [kk][r]
    __shared__ float Bs[32 * 64];   // [kk][c]
    int tid = threadIdx.x;
    int b0 = blockIdx.x * 16, n0 = blockIdx.y * 64;
    int r0 = (tid & 7) * 2, c0 = (tid >> 3) * 4;
    int arow = tid & 15, akq = tid >> 4;
    unsigned long long acc00 = 0, acc01 = 0, acc10 = 0, acc11 = 0;

    for (int k0 = 0; k0 < XDIM; k0 += 32) {
        float4 av = *(const float4*)&g_X[(b0 + arow) * XDIM + k0 + akq * 4];
        As[(akq * 4 + 0) * 16 + arow] = av.x;
        As[(akq * 4 + 1) * 16 + arow] = av.y;
        As[(akq * 4 + 2) * 16 + arow] = av.z;
        As[(akq * 4 + 3) * 16 + arow] = av.w;
        #pragma unroll
        for (int i = 0; i < 4; i++) {
            int t4 = tid + i * 128, kk = t4 >> 4, c4 = t4 & 15;
            int krow = k0 + kk;
            float4 bv = make_float4(0.f, 0.f, 0.f, 0.f);
            if (krow < 13)      bv = *(const float4*)&W1[krow * 256 + n0 + c4 * 4];
            else if (krow >= 16) bv = *(const float4*)&W1[(krow - 3) * 256 + n0 + c4 * 4];
            *(float4*)&Bs[kk * 64 + c4 * 4] = bv;
        }
        __syncthreads();
        #pragma unroll
        for (int kk = 0; kk < 32; kk++) {
            float2 a = *(const float2*)&As[kk * 16 + r0];
            ulonglong2 b = *(const ulonglong2*)&Bs[kk * 64 + c0];
            unsigned long long a0 = pk2(a.x, a.x), a1 = pk2(a.y, a.y);
            acc00 = fma2(a0, b.x, acc00); acc01 = fma2(a0, b.y, acc01);
            acc10 = fma2(a1, b.x, acc10); acc11 = fma2(a1, b.y, acc11);
        }
        __syncthreads();
    }
    float2 v00 = up2(acc00), v01 = up2(acc01), v10 = up2(acc10), v11 = up2(acc11);
    float4 bb = *(const float4*)&b1[n0 + c0];
    float4 o0 = {fmaxf(v00.x + bb.x, 0.f), fmaxf(v00.y + bb.y, 0.f),
                 fmaxf(v01.x + bb.z, 0.f), fmaxf(v01.y + bb.w, 0.f)};
    float4 o1 = {fmaxf(v10.x + bb.x, 0.f), fmaxf(v10.y + bb.y, 0.f),
                 fmaxf(v11.x + bb.z, 0.f), fmaxf(v11.y + bb.w, 0.f)};
    *(float4*)&g_h1[(b0 + r0) * 256 + n0 + c0] = o0;
    *(float4*)&g_h1[(b0 + r0 + 1) * 256 + n0 + c0] = o1;
}

// ---------------- MLP2: (4096 x 256)@(256 x 128), relu, f32x2 ----------------
__global__ __launch_bounds__(128) void k_mlp2(const float* __restrict__ W2,
                                              const float* __restrict__ b2) {
    __shared__ float As[32 * 16];
    __shared__ float Bs[32 * 64];
    int tid = threadIdx.x;
    int b0 = blockIdx.x * 16, n0 = blockIdx.y * 64;
    int r0 = (tid & 7) * 2, c0 = (tid >> 3) * 4;
    int arow = tid & 15, akq = tid >> 4;
    unsigned long long acc00 = 0, acc01 = 0, acc10 = 0, acc11 = 0;

    for (int k0 = 0; k0 < 256; k0 += 32) {
        float4 av = *(const float4*)&g_h1[(b0 + arow) * 256 + k0 + akq * 4];
        As[(akq * 4 + 0) * 16 + arow] = av.x;
        As[(akq * 4 + 1) * 16 + arow] = av.y;
        As[(akq * 4 + 2) * 16 + arow] = av.z;
        As[(akq * 4 + 3) * 16 + arow] = av.w;
        #pragma unroll
        for (int i = 0; i < 4; i++) {
            int t4 = tid + i * 128, kk = t4 >> 4, c4 = t4 & 15;
            *(float4*)&Bs[kk * 64 + c4 * 4] =
                *(const float4*)&W2[(k0 + kk) * 128 + n0 + c4 * 4];
        }
        __syncthreads();
        #pragma unroll
        for (int kk = 0; kk < 32; kk++) {
            float2 a = *(const float2*)&As[kk * 16 + r0];
            ulonglong2 b = *(const ulonglong2*)&Bs[kk * 64 + c0];
            unsigned long long a0 = pk2(a.x, a.x), a1 = pk2(a.y, a.y);
            acc00 = fma2(a0, b.x, acc00); acc01 = fma2(a0, b.y, acc01);
            acc10 = fma2(a1, b.x, acc10); acc11 = fma2(a1, b.y, acc11);
        }
        __syncthreads();
    }
    float2 v00 = up2(acc00), v01 = up2(acc01), v10 = up2(acc10), v11 = up2(acc11);
    float4 bb = *(const float4*)&b2[n0 + c0];
    float4 o0 = {fmaxf(v00.x + bb.x, 0.f), fmaxf(v00.y + bb.y, 0.f),
                 fmaxf(v01.x + bb.z, 0.f), fmaxf(v01.y + bb.w, 0.f)};
    float4 o1 = {fmaxf(v10.x + bb.x, 0.f), fmaxf(v10.y + bb.y, 0.f),
                 fmaxf(v11.x + bb.z, 0.f), fmaxf(v11.y + bb.w, 0.f)};
    *(float4*)&g_h2[(b0 + r0) * 128 + n0 + c0] = o0;
    *(float4*)&g_h2[(b0 + r0 + 1) * 128 + n0 + c0] = o1;
}

// ---------------- MLP L3 + L4 + combine + sigmoid ----------------
__global__ __launch_bounds__(128) void k_final(const float* __restrict__ W3,
                                               const float* __restrict__ b3,
                                               const float* __restrict__ W4,
                                               const float* __restrict__ b4,
                                               const float* __restrict__ clinb,
                                               float* __restrict__ out) {
    __shared__ float W3s[128 * 64];
    __shared__ float hs[16 * 128];
    __shared__ float W4s[64];
    __shared__ float red[4];
    int tid = threadIdx.x;
    int b0 = blockIdx.x * 16;
    for (int t = tid; t < 128 * 64; t += 128) W3s[t] = W3[t];
    for (int t = tid; t < 16 * 128; t += 128) hs[t] = g_h2[b0 * 128 + t];
    if (tid < 64) W4s[tid] = W4[tid];
    __syncthreads();

    int sh = tid >> 6;
    int o = tid & 63;
    float w4 = W4s[o];
    float b3o = b3[o];
    for (int ss = 0; ss < 8; ss++) {
        int s = ss * 2 + sh;
        float acc = 0.f;
        #pragma unroll 8
        for (int k = 0; k < 128; k++) acc += hs[s * 128 + k] * W3s[k * 64 + o];
        float h3 = fmaxf(acc + b3o, 0.f);
        float p = h3 * w4;
        #pragma unroll
        for (int off = 16; off; off >>= 1) p += __shfl_down_sync(0xffffffffu, p, off);
        if ((tid & 31) == 0) red[tid >> 5] = p;
        __syncthreads();
        if (o == 0) {
            float d = fmaxf(red[sh * 2] + red[sh * 2 + 1] + b4[0], 0.f);
            int b = b0 + s;
            float cin = fmaxf(g_s1[b] + g_s2[b] + g_cadd + clinb[0], 0.f);
            float logit = g_lin[b] + cin + d;
            out[b] = 1.f / (1.f + expf(-logit));
        }
        __syncthreads();
    }
}

// ---------------- launch ----------------
extern "C" void kernel_launch(void* const* d_in, const int* in_sizes, int n_in,
                              void* d_out, int out_size) {
    const float* inputs     = (const float*)d_in[0];
    const float* emb_tables = (const float*)d_in[1];
    const float* linear_W   = (const float*)d_in[2];
    const float* linear_b   = (const float*)d_in[3];
    const float* W_cin0     = (const float*)d_in[4];
    const float* b_cin0     = (const float*)d_in[5];
    const float* W_cin1     = (const float*)d_in[6];
    const float* b_cin1     = (const float*)d_in[7];
    const float* cin_lin_W  = (const float*)d_in[8];
    const float* cin_lin_b  = (const float*)d_in[9];
    const float* d_W1       = (const float*)d_in[10];
    const float* d_b1       = (const float*)d_in[11];
    const float* d_W2       = (const float*)d_in[12];
    const float* d_b2       = (const float*)d_in[13];
    const float* d_W3       = (const float*)d_in[14];
    const float* d_b3       = (const float*)d_in[15];
    const float* d_W4       = (const float*)d_in[16];
    const float* d_b4       = (const float*)d_in[17];
    float* out = (float*)d_out;

    k_prepV<<<16, 256>>>(W_cin0, W_cin1, cin_lin_W);
    k_prepT3<<<6, 64>>>(W_cin0);
    k_prepFold<<<14, 256>>>(b_cin0, b_cin1, cin_lin_W);
    k_gather<<<512, 256>>>(inputs, emb_tables, linear_W, linear_b);
    k_cin<<<256, 128>>>();
    k_mlp1<<<dim3(256, 4), 128>>>(d_W1, d_b1);
    k_mlp2<<<dim3(256, 2), 128>>>(d_W2, d_b2);
    k_final<<<256, 128>>>(d_W3, d_b3, d_W4, d_b4, cin_lin_b, out);
}

// round 5
// speedup vs baseline: 1.6318x; 1.3582x over previous
#include <cuda_runtime.h>
#include <math.h>

#define BATCH   4096
#define VOCAB   100000
#define NTRI    3276
#define NPAIR2  351
#define NT4     1121
#define XDIM    224      // [0:13] dense, [13:16] zero pad, [16:224] emb (26*8)

typedef unsigned long long ull;

// ---------------- scratch (device globals) ----------------
__device__ __align__(16) float g_V[128 * 26];
__device__ __align__(16) float g_V0c[NPAIR2];
__device__ __align__(16) float g_T3[NPAIR2 * 26];
__device__ __align__(16) float4 g_Tc4[NT4];
__device__ int   g_runofs[NPAIR2];
__device__ __align__(16) float g_vb[32];
__device__ float g_cadd;
__device__ __align__(16) float g_X[BATCH * XDIM];
__device__ float g_lin[BATCH];
__device__ float g_s1[BATCH];
__device__ float g_s2[BATCH];
__device__ __align__(16) float g_h1[BATCH * 256];
__device__ __align__(16) float g_h2[BATCH * 128];

// ---------------- packed f32x2 helpers ----------------
__device__ __forceinline__ ull pk2(float lo, float hi) {
    ull r;
    asm("mov.b64 %0, {%1, %2};" : "=l"(r) : "f"(lo), "f"(hi));
    return r;
}
__device__ __forceinline__ ull fma2(ull a, ull b, ull c) {
    ull d;
    asm("fma.rn.f32x2 %0, %1, %2, %3;" : "=l"(d) : "l"(a), "l"(b), "l"(c));
    return d;
}
__device__ __forceinline__ float2 up2(ull v) {
    float2 f;
    asm("mov.b64 {%0, %1}, %2;" : "=f"(f.x), "=f"(f.y) : "l"(v));
    return f;
}

// ---------------- prep V: g_V (coalesced GEMV), zero Tc4, runofs, cadd ----------
__global__ void k_prepV(const float* __restrict__ W1, const float* __restrict__ clinW,
                        const float* __restrict__ b0, const float* __restrict__ b1) {
    int t0 = blockIdx.x * blockDim.x + threadIdx.x;
    int st = gridDim.x * blockDim.x;
    float* tc4f = (float*)g_Tc4;
    for (int u = t0; u < NT4 * 4; u += st) tc4f[u] = 0.f;
    for (int u = t0; u < 3328; u += st) {
        float s0 = 0.f, s1 = 0.f, s2 = 0.f, s3 = 0.f;
        #pragma unroll 8
        for (int o = 0; o < 128; o += 4) {
            s0 = fmaf(clinW[128 + o + 0], W1[(o + 0) * 3328 + u], s0);
            s1 = fmaf(clinW[128 + o + 1], W1[(o + 1) * 3328 + u], s1);
            s2 = fmaf(clinW[128 + o + 2], W1[(o + 2) * 3328 + u], s2);
            s3 = fmaf(clinW[128 + o + 3], W1[(o + 3) * 3328 + u], s3);
        }
        g_V[u] = (s0 + s1) + (s2 + s3);
    }
    for (int t2 = t0; t2 < NPAIR2; t2 += st) {
        int p = 0, rem = t2;
        while (rem >= 26 - p) { rem -= 26 - p; p++; }
        int q = p + rem;
        int s4 = 0;
        for (int pp = 0; pp < p; pp++)
            for (int qq = pp; qq < 26; qq++) s4 += 7 - (qq >> 2);
        for (int qq = p; qq < q; qq++) s4 += 7 - (qq >> 2);
        g_runofs[t2] = s4;
    }
    if (t0 < 32) {
        float s = 0.f;
        for (int o = t0; o < 128; o += 32)
            s += clinW[o] * b0[o] + clinW[128 + o] * b1[o];
        #pragma unroll
        for (int off = 16; off; off >>= 1) s += __shfl_down_sync(0xffffffffu, s, off);
        if (t0 == 0) g_cadd = 8.f * s;
    }
}

// ---------------- prep T3 + V0c: warp per pq, broadcast W0, coalesced V ----------
__global__ __launch_bounds__(32) void k_prepT3(const float* __restrict__ W0,
                                               const float* __restrict__ clinW) {
    int pq = blockIdx.x;
    int p = 0, rem = pq;
    while (rem >= 26 - p) { rem -= 26 - p; p++; }
    int q = p + rem;
    int j = threadIdx.x;
    const float* wp = W0 + p * 26 + q;
    const float* wq = W0 + q * 26 + p;
    bool isV = (j == 26);
    bool isT = (j < 26);
    float a0 = 0.f, a1 = 0.f, a2 = 0.f, a3 = 0.f;
    if (p == q) {
        #pragma unroll 4
        for (int i = 0; i < 128; i += 4) {
            float w0 = __ldg(&wp[(i + 0) * 676]);
            float w1 = __ldg(&wp[(i + 1) * 676]);
            float w2 = __ldg(&wp[(i + 2) * 676]);
            float w3 = __ldg(&wp[(i + 3) * 676]);
            float v0 = isT ? g_V[(i + 0) * 26 + j] : (isV ? clinW[i + 0] : 0.f);
            float v1 = isT ? g_V[(i + 1) * 26 + j] : (isV ? clinW[i + 1] : 0.f);
            float v2 = isT ? g_V[(i + 2) * 26 + j] : (isV ? clinW[i + 2] : 0.f);
            float v3 = isT ? g_V[(i + 3) * 26 + j] : (isV ? clinW[i + 3] : 0.f);
            a0 = fmaf(w0, v0, a0); a1 = fmaf(w1, v1, a1);
            a2 = fmaf(w2, v2, a2); a3 = fmaf(w3, v3, a3);
        }
    } else {
        #pragma unroll 4
        for (int i = 0; i < 128; i += 4) {
            float w0 = __ldg(&wp[(i + 0) * 676]) + __ldg(&wq[(i + 0) * 676]);
            float w1 = __ldg(&wp[(i + 1) * 676]) + __ldg(&wq[(i + 1) * 676]);
            float w2 = __ldg(&wp[(i + 2) * 676]) + __ldg(&wq[(i + 2) * 676]);
            float w3 = __ldg(&wp[(i + 3) * 676]) + __ldg(&wq[(i + 3) * 676]);
            float v0 = isT ? g_V[(i + 0) * 26 + j] : (isV ? clinW[i + 0] : 0.f);
            float v1 = isT ? g_V[(i + 1) * 26 + j] : (isV ? clinW[i + 1] : 0.f);
            float v2 = isT ? g_V[(i + 2) * 26 + j] : (isV ? clinW[i + 2] : 0.f);
            float v3 = isT ? g_V[(i + 3) * 26 + j] : (isV ? clinW[i + 3] : 0.f);
            a0 = fmaf(w0, v0, a0); a1 = fmaf(w1, v1, a1);
            a2 = fmaf(w2, v2, a2); a3 = fmaf(w3, v3, a3);
        }
    }
    float s = (a0 + a1) + (a2 + a3);
    if (isT) g_T3[pq * 26 + j] = s;
    else if (isV) g_V0c[pq] = s;
}

// ---------------- prep fold: triples -> padded runs; vb ----------------
__device__ __forceinline__ int pidx(int a, int b) {
    return a * 26 - a * (a - 1) / 2 + (b - a);
}
__global__ void k_prepFold(const float* __restrict__ b0) {
    int t = blockIdx.x * blockDim.x + threadIdx.x;
    if (t < NTRI) {
        int rem = t, p = 0;
        while (true) { int c = (26 - p) * (27 - p) / 2; if (rem < c) break; rem -= c; p++; }
        int q = p;
        while (true) { int c = 26 - q; if (rem < c) break; rem -= c; q++; }
        int j = q + rem;
        float v;
        if (p == q && q == j)
            v = g_T3[pidx(p, p) * 26 + p];
        else if (p == q)
            v = g_T3[pidx(p, p) * 26 + j] + g_T3[pidx(p, j) * 26 + p];
        else if (q == j)
            v = g_T3[pidx(p, q) * 26 + q] + g_T3[pidx(q, q) * 26 + p];
        else
            v = g_T3[pidx(p, q) * 26 + j] + g_T3[pidx(p, j) * 26 + q]
              + g_T3[pidx(q, j) * 26 + p];
        int q0 = q & ~3;
        ((float*)g_Tc4)[g_runofs[pidx(p, q)] * 4 + (j - q0)] = v;
    } else if (t < NTRI + 26) {
        int j = t - NTRI;
        float s = 0.f;
        #pragma unroll 4
        for (int i = 0; i < 128; i++) s = fmaf(g_V[i * 26 + j], b0[i], s);
        g_vb[j] = s;
    }
}

// ---------------- gather: build padded g_X + linear term ----------------
__global__ void k_gather(const float* __restrict__ inputs,
                         const float* __restrict__ emb_tables,
                         const float* __restrict__ linW,
                         const float* __restrict__ linb) {
    int warp = (blockIdx.x * blockDim.x + threadIdx.x) >> 5;
    int lane = threadIdx.x & 31;
    if (warp >= BATCH) return;
    int b = warp;
    const float* row = inputs + b * 39;
    if (lane < 13) g_X[b * XDIM + lane] = row[lane];
    else if (lane < 16) g_X[b * XDIM + lane] = 0.f;
    if (lane < 26) {
        int idx = (int)row[13 + lane];
        const float4* src = (const float4*)(emb_tables + ((size_t)lane * VOCAB + idx) * 8);
        float4* dst = (float4*)(g_X + b * XDIM + 16 + lane * 8);
        dst[0] = src[0];
        dst[1] = src[1];
    }
    float s = 0.f;
    for (int t = lane; t < 39; t += 32) s += row[t] * linW[t];
    #pragma unroll
    for (int o = 16; o; o >>= 1) s += __shfl_down_sync(0xffffffffu, s, o);
    if (lane == 0) g_lin[b] = s + linb[0];
}

// ---------------- CIN: third-moment contraction, e in registers ----------------
__global__ __launch_bounds__(128) void k_cin() {
    __shared__ float4 Tc4s[NT4];
    __shared__ float V0s[NPAIR2];
    __shared__ float vbs[32];
    int tid = threadIdx.x;
    int b0 = blockIdx.x * 16;
    for (int t = tid; t < NT4; t += 128) Tc4s[t] = g_Tc4[t];
    for (int t = tid; t < NPAIR2; t += 128) V0s[t] = g_V0c[t];
    if (tid < 26) vbs[tid] = g_vb[tid];

    int bl = tid >> 3, k = tid & 7;
    const float* eb = g_X + (b0 + bl) * XDIM + 16 + k;
    float e[28];
    #pragma unroll
    for (int j = 0; j < 26; j++) e[j] = eb[j * 8];
    e[26] = 0.f; e[27] = 0.f;
    __syncthreads();

    float s1p = 0.f, s2p = 0.f;
    int t4 = 0, t2 = 0;
    #pragma unroll
    for (int p = 0; p < 26; p++) {
        #pragma unroll
        for (int q = p; q < 26; q++) {
            float w = e[p] * e[q];
            s1p = fmaf(V0s[t2], w, s1p); t2++;
            float d = 0.f;
            #pragma unroll
            for (int j4 = (q & ~3); j4 < 28; j4 += 4) {
                float4 tc = Tc4s[t4]; t4++;
                d = fmaf(tc.x, e[j4 + 0], d);
                d = fmaf(tc.y, e[j4 + 1], d);
                d = fmaf(tc.z, e[j4 + 2], d);
                d = fmaf(tc.w, e[j4 + 3], d);
            }
            s2p = fmaf(w, d, s2p);
        }
    }
    #pragma unroll
    for (int j = 0; j < 26; j++) s2p = fmaf(vbs[j], e[j], s2p);

    #pragma unroll
    for (int off = 4; off; off >>= 1) {
        s1p += __shfl_down_sync(0xffffffffu, s1p, off, 8);
        s2p += __shfl_down_sync(0xffffffffu, s2p, off, 8);
    }
    if (k == 0) {
        g_s1[b0 + bl] = s1p;
        g_s2[b0 + bl] = s2p;
    }
}

// ---------------- MLP1: (4096 x 224)@(224 x 256), relu, f32x2, dup'd-B smem ----
__global__ __launch_bounds__(128) void k_mlp1(const float* __restrict__ W1,
                                              const float* __restrict__ b1) {
    __shared__ __align__(16) float As[32 * 32];   // [kk][r]
    __shared__ __align__(16) ull Bs[32 * 64];     // [kk][c] duplicated pairs
    int tid = threadIdx.x;
    int b0 = blockIdx.x * 32, n0 = blockIdx.y * 64;
    int r0 = (tid & 7) * 4;
    int c0 = (tid >> 3) * 4;
    int arow = tid & 31, akq = tid >> 5;
    ull acc[2][4];
    #pragma unroll
    for (int i = 0; i < 2; i++)
        #pragma unroll
        for (int c = 0; c < 4; c++) acc[i][c] = 0ull;

    for (int k0 = 0; k0 < XDIM; k0 += 32) {
        #pragma unroll
        for (int i = 0; i < 2; i++) {
            int kb = akq * 4 + i * 16;
            float4 v = *(const float4*)&g_X[(b0 + arow) * XDIM + k0 + kb];
            As[(kb + 0) * 32 + arow] = v.x;
            As[(kb + 1) * 32 + arow] = v.y;
            As[(kb + 2) * 32 + arow] = v.z;
            As[(kb + 3) * 32 + arow] = v.w;
        }
        #pragma unroll
        for (int i = 0; i < 4; i++) {
            int t4 = tid + i * 128;
            int kk = t4 >> 4, c4 = t4 & 15;
            int krow = k0 + kk;
            float4 w = make_float4(0.f, 0.f, 0.f, 0.f);
            if (krow < 13)       w = *(const float4*)&W1[krow * 256 + n0 + c4 * 4];
            else if (krow >= 16) w = *(const float4*)&W1[(krow - 3) * 256 + n0 + c4 * 4];
            ulonglong2 d0 = {pk2(w.x, w.x), pk2(w.y, w.y)};
            ulonglong2 d1 = {pk2(w.z, w.z), pk2(w.w, w.w)};
            *(ulonglong2*)&Bs[kk * 64 + c4 * 4] = d0;
            *(ulonglong2*)&Bs[kk * 64 + c4 * 4 + 2] = d1;
        }
        __syncthreads();
        #pragma unroll
        for (int kk = 0; kk < 32; kk++) {
            ulonglong2 av = *(const ulonglong2*)&As[kk * 32 + r0];
            ulonglong2 bv0 = *(const ulonglong2*)&Bs[kk * 64 + c0];
            ulonglong2 bv1 = *(const ulonglong2*)&Bs[kk * 64 + c0 + 2];
            acc[0][0] = fma2(av.x, bv0.x, acc[0][0]);
            acc[0][1] = fma2(av.x, bv0.y, acc[0][1]);
            acc[0][2] = fma2(av.x, bv1.x, acc[0][2]);
            acc[0][3] = fma2(av.x, bv1.y, acc[0][3]);
            acc[1][0] = fma2(av.y, bv0.x, acc[1][0]);
            acc[1][1] = fma2(av.y, bv0.y, acc[1][1]);
            acc[1][2] = fma2(av.y, bv1.x, acc[1][2]);
            acc[1][3] = fma2(av.y, bv1.y, acc[1][3]);
        }
        __syncthreads();
    }
    float4 bb = *(const float4*)&b1[n0 + c0];
    #pragma unroll
    for (int rp = 0; rp < 2; rp++) {
        float2 x0 = up2(acc[rp][0]), x1 = up2(acc[rp][1]);
        float2 x2 = up2(acc[rp][2]), x3 = up2(acc[rp][3]);
        int row = b0 + r0 + rp * 2;
        float4 o0 = {fmaxf(x0.x + bb.x, 0.f), fmaxf(x1.x + bb.y, 0.f),
                     fmaxf(x2.x + bb.z, 0.f), fmaxf(x3.x + bb.w, 0.f)};
        float4 o1 = {fmaxf(x0.y + bb.x, 0.f), fmaxf(x1.y + bb.y, 0.f),
                     fmaxf(x2.y + bb.z, 0.f), fmaxf(x3.y + bb.w, 0.f)};
        *(float4*)&g_h1[row * 256 + n0 + c0] = o0;
        *(float4*)&g_h1[(row + 1) * 256 + n0 + c0] = o1;
    }
}

// ---------------- MLP2: (4096 x 256)@(256 x 128), relu, f32x2, dup'd-B smem ----
__global__ __launch_bounds__(128) void k_mlp2(const float* __restrict__ W2,
                                              const float* __restrict__ b2) {
    __shared__ __align__(16) float As[32 * 32];
    __shared__ __align__(16) ull Bs[32 * 64];
    int tid = threadIdx.x;
    int b0 = blockIdx.x * 32, n0 = blockIdx.y * 64;
    int r0 = (tid & 7) * 4;
    int c0 = (tid >> 3) * 4;
    int arow = tid & 31, akq = tid >> 5;
    ull acc[2][4];
    #pragma unroll
    for (int i = 0; i < 2; i++)
        #pragma unroll
        for (int c = 0; c < 4; c++) acc[i][c] = 0ull;

    for (int k0 = 0; k0 < 256; k0 += 32) {
        #pragma unroll
        for (int i = 0; i < 2; i++) {
            int kb = akq * 4 + i * 16;
            float4 v = *(const float4*)&g_h1[(b0 + arow) * 256 + k0 + kb];
            As[(kb + 0) * 32 + arow] = v.x;
            As[(kb + 1) * 32 + arow] = v.y;
            As[(kb + 2) * 32 + arow] = v.z;
            As[(kb + 3) * 32 + arow] = v.w;
        }
        #pragma unroll
        for (int i = 0; i < 4; i++) {
            int t4 = tid + i * 128;
            int kk = t4 >> 4, c4 = t4 & 15;
            float4 w = *(const float4*)&W2[(k0 + kk) * 128 + n0 + c4 * 4];
            ulonglong2 d0 = {pk2(w.x, w.x), pk2(w.y, w.y)};
            ulonglong2 d1 = {pk2(w.z, w.z), pk2(w.w, w.w)};
            *(ulonglong2*)&Bs[kk * 64 + c4 * 4] = d0;
            *(ulonglong2*)&Bs[kk * 64 + c4 * 4 + 2] = d1;
        }
        __syncthreads();
        #pragma unroll
        for (int kk = 0; kk < 32; kk++) {
            ulonglong2 av = *(const ulonglong2*)&As[kk * 32 + r0];
            ulonglong2 bv0 = *(const ulonglong2*)&Bs[kk * 64 + c0];
            ulonglong2 bv1 = *(const ulonglong2*)&Bs[kk * 64 + c0 + 2];
            acc[0][0] = fma2(av.x, bv0.x, acc[0][0]);
            acc[0][1] = fma2(av.x, bv0.y, acc[0][1]);
            acc[0][2] = fma2(av.x, bv1.x, acc[0][2]);
            acc[0][3] = fma2(av.x, bv1.y, acc[0][3]);
            acc[1][0] = fma2(av.y, bv0.x, acc[1][0]);
            acc[1][1] = fma2(av.y, bv0.y, acc[1][1]);
            acc[1][2] = fma2(av.y, bv1.x, acc[1][2]);
            acc[1][3] = fma2(av.y, bv1.y, acc[1][3]);
        }
        __syncthreads();
    }
    float4 bb = *(const float4*)&b2[n0 + c0];
    #pragma unroll
    for (int rp = 0; rp < 2; rp++) {
        float2 x0 = up2(acc[rp][0]), x1 = up2(acc[rp][1]);
        float2 x2 = up2(acc[rp][2]), x3 = up2(acc[rp][3]);
        int row = b0 + r0 + rp * 2;
        float4 o0 = {fmaxf(x0.x + bb.x, 0.f), fmaxf(x1.x + bb.y, 0.f),
                     fmaxf(x2.x + bb.z, 0.f), fmaxf(x3.x + bb.w, 0.f)};
        float4 o1 = {fmaxf(x0.y + bb.x, 0.f), fmaxf(x1.y + bb.y, 0.f),
                     fmaxf(x2.y + bb.z, 0.f), fmaxf(x3.y + bb.w, 0.f)};
        *(float4*)&g_h2[row * 128 + n0 + c0] = o0;
        *(float4*)&g_h2[(row + 1) * 128 + n0 + c0] = o1;
    }
}

// ---------------- MLP L3 + L4 + combine + sigmoid ----------------
__global__ __launch_bounds__(128) void k_final(const float* __restrict__ W3,
                                               const float* __restrict__ b3,
                                               const float* __restrict__ W4,
                                               const float* __restrict__ b4,
                                               const float* __restrict__ clinb,
                                               float* __restrict__ out) {
    __shared__ float W3s[128 * 64];
    __shared__ float hs[16 * 128];
    __shared__ float W4s[64];
    __shared__ float red[4];
    int tid = threadIdx.x;
    int b0 = blockIdx.x * 16;
    for (int t = tid; t < 128 * 64; t += 128) W3s[t] = W3[t];
    for (int t = tid; t < 16 * 128; t += 128) hs[t] = g_h2[b0 * 128 + t];
    if (tid < 64) W4s[tid] = W4[tid];
    __syncthreads();

    int sh = tid >> 6;
    int o = tid & 63;
    float w4 = W4s[o];
    float b3o = b3[o];
    for (int ss = 0; ss < 8; ss++) {
        int s = ss * 2 + sh;
        float acc = 0.f;
        #pragma unroll 8
        for (int k = 0; k < 128; k++) acc += hs[s * 128 + k] * W3s[k * 64 + o];
        float h3 = fmaxf(acc + b3o, 0.f);
        float p = h3 * w4;
        #pragma unroll
        for (int off = 16; off; off >>= 1) p += __shfl_down_sync(0xffffffffu, p, off);
        if ((tid & 31) == 0) red[tid >> 5] = p;
        __syncthreads();
        if (o == 0) {
            float d = fmaxf(red[sh * 2] + red[sh * 2 + 1] + b4[0], 0.f);
            int b = b0 + s;
            float cin = fmaxf(g_s1[b] + g_s2[b] + g_cadd + clinb[0], 0.f);
            float logit = g_lin[b] + cin + d;
            out[b] = 1.f / (1.f + expf(-logit));
        }
        __syncthreads();
    }
}

// ---------------- launch ----------------
extern "C" void kernel_launch(void* const* d_in, const int* in_sizes, int n_in,
                              void* d_out, int out_size) {
    const float* inputs     = (const float*)d_in[0];
    const float* emb_tables = (const float*)d_in[1];
    const float* linear_W   = (const float*)d_in[2];
    const float* linear_b   = (const float*)d_in[3];
    const float* W_cin0     = (const float*)d_in[4];
    const float* b_cin0     = (const float*)d_in[5];
    const float* W_cin1     = (const float*)d_in[6];
    const float* b_cin1     = (const float*)d_in[7];
    const float* cin_lin_W  = (const float*)d_in[8];
    const float* cin_lin_b  = (const float*)d_in[9];
    const float* d_W1       = (const float*)d_in[10];
    const float* d_b1       = (const float*)d_in[11];
    const float* d_W2       = (const float*)d_in[12];
    const float* d_b2       = (const float*)d_in[13];
    const float* d_W3       = (const float*)d_in[14];
    const float* d_b3       = (const float*)d_in[15];
    const float* d_W4       = (const float*)d_in[16];
    const float* d_b4       = (const float*)d_in[17];
    float* out = (float*)d_out;

    k_prepV<<<32, 256>>>(W_cin1, cin_lin_W, b_cin0, b_cin1);
    k_prepT3<<<NPAIR2, 32>>>(W_cin0, cin_lin_W);
    k_prepFold<<<13, 256>>>(b_cin0);
    k_gather<<<512, 256>>>(inputs, emb_tables, linear_W, linear_b);
    k_cin<<<256, 128>>>();
    k_mlp1<<<dim3(128, 4), 128>>>(d_W1, d_b1);
    k_mlp2<<<dim3(128, 2), 128>>>(d_W2, d_b2);
    k_final<<<256, 128>>>(d_W3, d_b3, d_W4, d_b4, cin_lin_b, out);
}

// round 7
// speedup vs baseline: 1.8527x; 1.1354x over previous
#include <cuda_runtime.h>
#include <math.h>

#define BATCH   4096
#define VOCAB   100000
#define NTRI    3276
#define NPAIR2  351
#define NT4     1121
#define XDIM    224      // [0:13] dense, [13:16] zero pad, [16:224] emb (26*8)

typedef unsigned long long ull;

// ---------------- scratch (device globals) ----------------
__device__ __align__(16) float g_V[128 * 26];
__device__ __align__(16) float g_V0c[NPAIR2];
__device__ __align__(16) float g_T3[NPAIR2 * 26];
__device__ __align__(16) float4 g_Tc4[NT4];
__device__ int   g_runofs[NPAIR2];
__device__ __align__(16) float g_vb[32];
__device__ float g_cadd;
__device__ __align__(16) float g_X[BATCH * XDIM];
__device__ float g_lin[BATCH];
__device__ float g_s1[BATCH];
__device__ float g_s2[BATCH];
__device__ __align__(16) float g_h1[BATCH * 256];
__device__ __align__(16) float g_h2[BATCH * 128];

// ---------------- packed f32x2 helpers ----------------
__device__ __forceinline__ ull pk2(float lo, float hi) {
    ull r;
    asm("mov.b64 %0, {%1, %2};" : "=l"(r) : "f"(lo), "f"(hi));
    return r;
}
__device__ __forceinline__ ull fma2(ull a, ull b, ull c) {
    ull d;
    asm("fma.rn.f32x2 %0, %1, %2, %3;" : "=l"(d) : "l"(a), "l"(b), "l"(c));
    return d;
}
__device__ __forceinline__ float2 up2(ull v) {
    float2 f;
    asm("mov.b64 {%0, %1}, %2;" : "=f"(f.x), "=f"(f.y) : "l"(v));
    return f;
}

// ================= K1: gather (blocks 0..431)  ||  prepV (blocks 432..463) =====
__global__ __launch_bounds__(256) void k_front(const float* __restrict__ inputs,
                                               const float* __restrict__ emb_tables,
                                               const float* __restrict__ linW,
                                               const float* __restrict__ linb,
                                               const float* __restrict__ W1,
                                               const float* __restrict__ clinW,
                                               const float* __restrict__ b0,
                                               const float* __restrict__ b1) {
    int bx = blockIdx.x;
    if (bx < 416) {
        // emb copy: thread per (sample, field)
        int t = bx * 256 + threadIdx.x;
        int b = t / 26, f = t - b * 26;
        int idx = (int)inputs[b * 39 + 13 + f];
        const float4* src = (const float4*)(emb_tables + ((size_t)f * VOCAB + idx) * 8);
        float4* dst = (float4*)(g_X + b * XDIM + 16 + f * 8);
        dst[0] = src[0];
        dst[1] = src[1];
    } else if (bx < 432) {
        // dense + linear: thread per sample
        int b = (bx - 416) * 256 + threadIdx.x;
        const float* row = inputs + b * 39;
        float lin = linb[0];
        #pragma unroll
        for (int k = 0; k < 13; k++) {
            float v = row[k];
            g_X[b * XDIM + k] = v;
            lin = fmaf(v, linW[k], lin);
        }
        g_X[b * XDIM + 13] = 0.f;
        g_X[b * XDIM + 14] = 0.f;
        g_X[b * XDIM + 15] = 0.f;
        #pragma unroll
        for (int k = 13; k < 39; k++) lin = fmaf(row[k], linW[k], lin);
        g_lin[b] = lin;
    } else {
        // prepV: g_V GEMV, zero Tc4, runofs, cadd
        int t0 = (bx - 432) * 256 + threadIdx.x;
        const int st = 32 * 256;
        float* tc4f = (float*)g_Tc4;
        for (int u = t0; u < NT4 * 4; u += st) tc4f[u] = 0.f;
        for (int u = t0; u < 3328; u += st) {
            float s0 = 0.f, s1 = 0.f, s2 = 0.f, s3 = 0.f;
            #pragma unroll 8
            for (int o = 0; o < 128; o += 4) {
                s0 = fmaf(clinW[128 + o + 0], W1[(o + 0) * 3328 + u], s0);
                s1 = fmaf(clinW[128 + o + 1], W1[(o + 1) * 3328 + u], s1);
                s2 = fmaf(clinW[128 + o + 2], W1[(o + 2) * 3328 + u], s2);
                s3 = fmaf(clinW[128 + o + 3], W1[(o + 3) * 3328 + u], s3);
            }
            g_V[u] = (s0 + s1) + (s2 + s3);
        }
        for (int t2 = t0; t2 < NPAIR2; t2 += st) {
            int p = 0, rem = t2;
            while (rem >= 26 - p) { rem -= 26 - p; p++; }
            int q = p + rem;
            int s4 = 0;
            for (int pp = 0; pp < p; pp++)
                for (int qq = pp; qq < 26; qq++) s4 += 7 - (qq >> 2);
            for (int qq = p; qq < q; qq++) s4 += 7 - (qq >> 2);
            g_runofs[t2] = s4;
        }
        if (t0 < 32) {
            float s = 0.f;
            for (int o = t0; o < 128; o += 32)
                s += clinW[o] * b0[o] + clinW[128 + o] * b1[o];
            #pragma unroll
            for (int off = 16; off; off >>= 1) s += __shfl_down_sync(0xffffffffu, s, off);
            if (t0 == 0) g_cadd = 8.f * s;
        }
    }
}

// ================= K2: prepT3 + V0c (4 warps/block, warp per pq) =================
__global__ __launch_bounds__(128) void k_prepT3(const float* __restrict__ W0,
                                                const float* __restrict__ clinW) {
    int pq = blockIdx.x * 4 + (threadIdx.x >> 5);
    if (pq >= NPAIR2) return;
    int p = 0, rem = pq;
    while (rem >= 26 - p) { rem -= 26 - p; p++; }
    int q = p + rem;
    int j = threadIdx.x & 31;
    const float* wp = W0 + p * 26 + q;
    const float* wq = W0 + q * 26 + p;
    bool isV = (j == 26);
    bool isT = (j < 26);
    float a0 = 0.f, a1 = 0.f, a2 = 0.f, a3 = 0.f;
    if (p == q) {
        #pragma unroll 4
        for (int i = 0; i < 128; i += 4) {
            float w0 = __ldg(&wp[(i + 0) * 676]);
            float w1 = __ldg(&wp[(i + 1) * 676]);
            float w2 = __ldg(&wp[(i + 2) * 676]);
            float w3 = __ldg(&wp[(i + 3) * 676]);
            float v0 = isT ? g_V[(i + 0) * 26 + j] : (isV ? clinW[i + 0] : 0.f);
            float v1 = isT ? g_V[(i + 1) * 26 + j] : (isV ? clinW[i + 1] : 0.f);
            float v2 = isT ? g_V[(i + 2) * 26 + j] : (isV ? clinW[i + 2] : 0.f);
            float v3 = isT ? g_V[(i + 3) * 26 + j] : (isV ? clinW[i + 3] : 0.f);
            a0 = fmaf(w0, v0, a0); a1 = fmaf(w1, v1, a1);
            a2 = fmaf(w2, v2, a2); a3 = fmaf(w3, v3, a3);
        }
    } else {
        #pragma unroll 4
        for (int i = 0; i < 128; i += 4) {
            float w0 = __ldg(&wp[(i + 0) * 676]) + __ldg(&wq[(i + 0) * 676]);
            float w1 = __ldg(&wp[(i + 1) * 676]) + __ldg(&wq[(i + 1) * 676]);
            float w2 = __ldg(&wp[(i + 2) * 676]) + __ldg(&wq[(i + 2) * 676]);
            float w3 = __ldg(&wp[(i + 3) * 676]) + __ldg(&wq[(i + 3) * 676]);
            float v0 = isT ? g_V[(i + 0) * 26 + j] : (isV ? clinW[i + 0] : 0.f);
            float v1 = isT ? g_V[(i + 1) * 26 + j] : (isV ? clinW[i + 1] : 0.f);
            float v2 = isT ? g_V[(i + 2) * 26 + j] : (isV ? clinW[i + 2] : 0.f);
            float v3 = isT ? g_V[(i + 3) * 26 + j] : (isV ? clinW[i + 3] : 0.f);
            a0 = fmaf(w0, v0, a0); a1 = fmaf(w1, v1, a1);
            a2 = fmaf(w2, v2, a2); a3 = fmaf(w3, v3, a3);
        }
    }
    float s = (a0 + a1) + (a2 + a3);
    if (isT) g_T3[pq * 26 + j] = s;
    else if (isV) g_V0c[pq] = s;
}

__device__ __forceinline__ int pidx(int a, int b) {
    return a * 26 - a * (a - 1) / 2 + (b - a);
}

// ================= K3: mlp1 (blocks 0..511)  ||  prepFold (blocks 512..537) =====
__global__ __launch_bounds__(128) void k_mid(const float* __restrict__ W1,
                                             const float* __restrict__ b1,
                                             const float* __restrict__ b0cin) {
    __shared__ __align__(16) float As[32 * 32];
    __shared__ __align__(16) ull Bs[32 * 64];
    int blk = blockIdx.x;
    int tid = threadIdx.x;
    if (blk >= 512) {
        // prepFold
        int t = (blk - 512) * 128 + tid;
        if (t < NTRI) {
            int rem = t, p = 0;
            while (true) { int c = (26 - p) * (27 - p) / 2; if (rem < c) break; rem -= c; p++; }
            int q = p;
            while (true) { int c = 26 - q; if (rem < c) break; rem -= c; q++; }
            int j = q + rem;
            float v;
            if (p == q && q == j)
                v = g_T3[pidx(p, p) * 26 + p];
            else if (p == q)
                v = g_T3[pidx(p, p) * 26 + j] + g_T3[pidx(p, j) * 26 + p];
            else if (q == j)
                v = g_T3[pidx(p, q) * 26 + q] + g_T3[pidx(q, q) * 26 + p];
            else
                v = g_T3[pidx(p, q) * 26 + j] + g_T3[pidx(p, j) * 26 + q]
                  + g_T3[pidx(q, j) * 26 + p];
            int q0 = q & ~3;
            ((float*)g_Tc4)[g_runofs[pidx(p, q)] * 4 + (j - q0)] = v;
        } else if (t < NTRI + 26) {
            int j = t - NTRI;
            float s = 0.f;
            #pragma unroll 4
            for (int i = 0; i < 128; i++) s = fmaf(g_V[i * 26 + j], b0cin[i], s);
            g_vb[j] = s;
        }
        return;
    }
    // mlp1: (4096 x 224)@(224 x 256), relu, f32x2
    int b0 = (blk >> 2) * 32, n0 = (blk & 3) * 64;
    int r0 = (tid & 7) * 4;
    int c0 = (tid >> 3) * 4;
    int arow = tid & 31, akq = tid >> 5;
    ull acc[2][4];
    #pragma unroll
    for (int i = 0; i < 2; i++)
        #pragma unroll
        for (int c = 0; c < 4; c++) acc[i][c] = 0ull;

    for (int k0 = 0; k0 < XDIM; k0 += 32) {
        #pragma unroll
        for (int i = 0; i < 2; i++) {
            int kb = akq * 4 + i * 16;
            float4 v = *(const float4*)&g_X[(b0 + arow) * XDIM + k0 + kb];
            As[(kb + 0) * 32 + arow] = v.x;
            As[(kb + 1) * 32 + arow] = v.y;
            As[(kb + 2) * 32 + arow] = v.z;
            As[(kb + 3) * 32 + arow] = v.w;
        }
        #pragma unroll
        for (int i = 0; i < 4; i++) {
            int t4 = tid + i * 128;
            int kk = t4 >> 4, c4 = t4 & 15;
            int krow = k0 + kk;
            float4 w = make_float4(0.f, 0.f, 0.f, 0.f);
            if (krow < 13)       w = *(const float4*)&W1[krow * 256 + n0 + c4 * 4];
            else if (krow >= 16) w = *(const float4*)&W1[(krow - 3) * 256 + n0 + c4 * 4];
            ulonglong2 d0 = {pk2(w.x, w.x), pk2(w.y, w.y)};
            ulonglong2 d1 = {pk2(w.z, w.z), pk2(w.w, w.w)};
            *(ulonglong2*)&Bs[kk * 64 + c4 * 4] = d0;
            *(ulonglong2*)&Bs[kk * 64 + c4 * 4 + 2] = d1;
        }
        __syncthreads();
        #pragma unroll
        for (int kk = 0; kk < 32; kk++) {
            ulonglong2 av = *(const ulonglong2*)&As[kk * 32 + r0];
            ulonglong2 bv0 = *(const ulonglong2*)&Bs[kk * 64 + c0];
            ulonglong2 bv1 = *(const ulonglong2*)&Bs[kk * 64 + c0 + 2];
            acc[0][0] = fma2(av.x, bv0.x, acc[0][0]);
            acc[0][1] = fma2(av.x, bv0.y, acc[0][1]);
            acc[0][2] = fma2(av.x, bv1.x, acc[0][2]);
            acc[0][3] = fma2(av.x, bv1.y, acc[0][3]);
            acc[1][0] = fma2(av.y, bv0.x, acc[1][0]);
            acc[1][1] = fma2(av.y, bv0.y, acc[1][1]);
            acc[1][2] = fma2(av.y, bv1.x, acc[1][2]);
            acc[1][3] = fma2(av.y, bv1.y, acc[1][3]);
        }
        __syncthreads();
    }
    float4 bb = *(const float4*)&b1[n0 + c0];
    #pragma unroll
    for (int rp = 0; rp < 2; rp++) {
        float2 x0 = up2(acc[rp][0]), x1 = up2(acc[rp][1]);
        float2 x2 = up2(acc[rp][2]), x3 = up2(acc[rp][3]);
        int row = b0 + r0 + rp * 2;
        float4 o0 = {fmaxf(x0.x + bb.x, 0.f), fmaxf(x1.x + bb.y, 0.f),
                     fmaxf(x2.x + bb.z, 0.f), fmaxf(x3.x + bb.w, 0.f)};
        float4 o1 = {fmaxf(x0.y + bb.x, 0.f), fmaxf(x1.y + bb.y, 0.f),
                     fmaxf(x2.y + bb.z, 0.f), fmaxf(x3.y + bb.w, 0.f)};
        *(float4*)&g_h1[row * 256 + n0 + c0] = o0;
        *(float4*)&g_h1[(row + 1) * 256 + n0 + c0] = o1;
    }
}

// ================= K4: cin (blocks 0..255)  ||  mlp2 (blocks 256..511) ==========
__global__ __launch_bounds__(128) void k_back(const float* __restrict__ W2,
                                              const float* __restrict__ b2) {
    __shared__ float4 Tc4s[NT4];
    __shared__ float V0s[NPAIR2];
    __shared__ float vbs[32];
    __shared__ __align__(16) float As[32 * 32];
    __shared__ __align__(16) ull Bs[32 * 64];
    int blk = blockIdx.x;
    int tid = threadIdx.x;
    if (blk < 256) {
        // CIN third-moment contraction
        int b0 = blk * 16;
        for (int t = tid; t < NT4; t += 128) Tc4s[t] = g_Tc4[t];
        for (int t = tid; t < NPAIR2; t += 128) V0s[t] = g_V0c[t];
        if (tid < 26) vbs[tid] = g_vb[tid];

        int bl = tid >> 3, k = tid & 7;
        const float* eb = g_X + (b0 + bl) * XDIM + 16 + k;
        float e[28];
        #pragma unroll
        for (int j = 0; j < 26; j++) e[j] = eb[j * 8];
        e[26] = 0.f; e[27] = 0.f;
        __syncthreads();

        float s1p = 0.f, s2p = 0.f;
        int t4 = 0, t2 = 0;
        #pragma unroll
        for (int p = 0; p < 26; p++) {
            #pragma unroll
            for (int q = p; q < 26; q++) {
                float w = e[p] * e[q];
                s1p = fmaf(V0s[t2], w, s1p); t2++;
                float d = 0.f;
                #pragma unroll
                for (int j4 = (q & ~3); j4 < 28; j4 += 4) {
                    float4 tc = Tc4s[t4]; t4++;
                    d = fmaf(tc.x, e[j4 + 0], d);
                    d = fmaf(tc.y, e[j4 + 1], d);
                    d = fmaf(tc.z, e[j4 + 2], d);
                    d = fmaf(tc.w, e[j4 + 3], d);
                }
                s2p = fmaf(w, d, s2p);
            }
        }
        #pragma unroll
        for (int j = 0; j < 26; j++) s2p = fmaf(vbs[j], e[j], s2p);

        #pragma unroll
        for (int off = 4; off; off >>= 1) {
            s1p += __shfl_down_sync(0xffffffffu, s1p, off, 8);
            s2p += __shfl_down_sync(0xffffffffu, s2p, off, 8);
        }
        if (k == 0) {
            g_s1[b0 + bl] = s1p;
            g_s2[b0 + bl] = s2p;
        }
        return;
    }
    // mlp2: (4096 x 256)@(256 x 128), relu, f32x2
    int mb = blk - 256;
    int b0 = (mb >> 1) * 32, n0 = (mb & 1) * 64;
    int r0 = (tid & 7) * 4;
    int c0 = (tid >> 3) * 4;
    int arow = tid & 31, akq = tid >> 5;
    ull acc[2][4];
    #pragma unroll
    for (int i = 0; i < 2; i++)
        #pragma unroll
        for (int c = 0; c < 4; c++) acc[i][c] = 0ull;

    for (int k0 = 0; k0 < 256; k0 += 32) {
        #pragma unroll
        for (int i = 0; i < 2; i++) {
            int kb = akq * 4 + i * 16;
            float4 v = *(const float4*)&g_h1[(b0 + arow) * 256 + k0 + kb];
            As[(kb + 0) * 32 + arow] = v.x;
            As[(kb + 1) * 32 + arow] = v.y;
            As[(kb + 2) * 32 + arow] = v.z;
            As[(kb + 3) * 32 + arow] = v.w;
        }
        #pragma unroll
        for (int i = 0; i < 4; i++) {
            int t4 = tid + i * 128;
            int kk = t4 >> 4, c4 = t4 & 15;
            float4 w = *(const float4*)&W2[(k0 + kk) * 128 + n0 + c4 * 4];
            ulonglong2 d0 = {pk2(w.x, w.x), pk2(w.y, w.y)};
            ulonglong2 d1 = {pk2(w.z, w.z), pk2(w.w, w.w)};
            *(ulonglong2*)&Bs[kk * 64 + c4 * 4] = d0;
            *(ulonglong2*)&Bs[kk * 64 + c4 * 4 + 2] = d1;
        }
        __syncthreads();
        #pragma unroll
        for (int kk = 0; kk < 32; kk++) {
            ulonglong2 av = *(const ulonglong2*)&As[kk * 32 + r0];
            ulonglong2 bv0 = *(const ulonglong2*)&Bs[kk * 64 + c0];
            ulonglong2 bv1 = *(const ulonglong2*)&Bs[kk * 64 + c0 + 2];
            acc[0][0] = fma2(av.x, bv0.x, acc[0][0]);
            acc[0][1] = fma2(av.x, bv0.y, acc[0][1]);
            acc[0][2] = fma2(av.x, bv1.x, acc[0][2]);
            acc[0][3] = fma2(av.x, bv1.y, acc[0][3]);
            acc[1][0] = fma2(av.y, bv0.x, acc[1][0]);
            acc[1][1] = fma2(av.y, bv0.y, acc[1][1]);
            acc[1][2] = fma2(av.y, bv1.x, acc[1][2]);
            acc[1][3] = fma2(av.y, bv1.y, acc[1][3]);
        }
        __syncthreads();
    }
    float4 bb = *(const float4*)&b2[n0 + c0];
    #pragma unroll
    for (int rp = 0; rp < 2; rp++) {
        float2 x0 = up2(acc[rp][0]), x1 = up2(acc[rp][1]);
        float2 x2 = up2(acc[rp][2]), x3 = up2(acc[rp][3]);
        int row = b0 + r0 + rp * 2;
        float4 o0 = {fmaxf(x0.x + bb.x, 0.f), fmaxf(x1.x + bb.y, 0.f),
                     fmaxf(x2.x + bb.z, 0.f), fmaxf(x3.x + bb.w, 0.f)};
        float4 o1 = {fmaxf(x0.y + bb.x, 0.f), fmaxf(x1.y + bb.y, 0.f),
                     fmaxf(x2.y + bb.z, 0.f), fmaxf(x3.y + bb.w, 0.f)};
        *(float4*)&g_h2[row * 128 + n0 + c0] = o0;
        *(float4*)&g_h2[(row + 1) * 128 + n0 + c0] = o1;
    }
}

// ================= K5: MLP L3 + L4 + combine + sigmoid (warp per sample) ========
__global__ __launch_bounds__(128) void k_final(const float* __restrict__ W3,
                                               const float* __restrict__ b3,
                                               const float* __restrict__ W4,
                                               const float* __restrict__ b4,
                                               const float* __restrict__ clinb,
                                               float* __restrict__ out) {
    __shared__ float W3s[128 * 64];
    __shared__ float hs[16 * 128];
    int tid = threadIdx.x;
    int b0 = blockIdx.x * 16;
    for (int t = tid; t < 128 * 64; t += 128) W3s[t] = W3[t];
    for (int t = tid; t < 16 * 128; t += 128) hs[t] = g_h2[b0 * 128 + t];
    __syncthreads();

    int w = tid >> 5, lane = tid & 31;
    float b3a = b3[lane], b3b = b3[lane + 32];
    float w4a = W4[lane], w4b = W4[lane + 32];
    #pragma unroll
    for (int ss = 0; ss < 4; ss++) {
        int s = w * 4 + ss;
        float aa = 0.f, ab = 0.f;
        #pragma unroll 4
        for (int k = 0; k < 128; k++) {
            float h = hs[s * 128 + k];
            aa = fmaf(h, W3s[k * 64 + lane], aa);
            ab = fmaf(h, W3s[k * 64 + 32 + lane], ab);
        }
        float p = fmaxf(aa + b3a, 0.f) * w4a + fmaxf(ab + b3b, 0.f) * w4b;
        #pragma unroll
        for (int off = 16; off; off >>= 1) p += __shfl_down_sync(0xffffffffu, p, off);
        if (lane == 0) {
            int b = b0 + s;
            float d = fmaxf(p + b4[0], 0.f);
            float cin = fmaxf(g_s1[b] + g_s2[b] + g_cadd + clinb[0], 0.f);
            float logit = g_lin[b] + cin + d;
            out[b] = 1.f / (1.f + expf(-logit));
        }
    }
}

// ---------------- launch: 5 serial kernels, intra-kernel concurrency ----------
extern "C" void kernel_launch(void* const* d_in, const int* in_sizes, int n_in,
                              void* d_out, int out_size) {
    const float* inputs     = (const float*)d_in[0];
    const float* emb_tables = (const float*)d_in[1];
    const float* linear_W   = (const float*)d_in[2];
    const float* linear_b   = (const float*)d_in[3];
    const float* W_cin0     = (const float*)d_in[4];
    const float* b_cin0     = (const float*)d_in[5];
    const float* W_cin1     = (const float*)d_in[6];
    const float* b_cin1     = (const float*)d_in[7];
    const float* cin_lin_W  = (const float*)d_in[8];
    const float* cin_lin_b  = (const float*)d_in[9];
    const float* d_W1       = (const float*)d_in[10];
    const float* d_b1       = (const float*)d_in[11];
    const float* d_W2       = (const float*)d_in[12];
    const float* d_b2       = (const float*)d_in[13];
    const float* d_W3       = (const float*)d_in[14];
    const float* d_b3       = (const float*)d_in[15];
    const float* d_W4       = (const float*)d_in[16];
    const float* d_b4       = (const float*)d_in[17];
    float* out = (float*)d_out;

    k_front<<<464, 256>>>(inputs, emb_tables, linear_W, linear_b,
                          W_cin1, cin_lin_W, b_cin0, b_cin1);
    k_prepT3<<<88, 128>>>(W_cin0, cin_lin_W);
    k_mid<<<538, 128>>>(d_W1, d_b1, b_cin0);
    k_back<<<512, 128>>>(d_W2, d_b2);
    k_final<<<256, 128>>>(d_W3, d_b3, d_W4, d_b4, cin_lin_b, out);
}